// round 16
// baseline (speedup 1.0000x reference)
#include <cuda_runtime.h>
#include <cuda_bf16.h>
#include <mma.h>
#include <math.h>
#include <stdint.h>

using namespace nvcuda;

#define TPB 256

// ---------------------------------------------------------------------------
// Persistent scratch (allocation-free __device__ globals, ~943 MB)
// ---------------------------------------------------------------------------
__device__ __nv_bfloat16 g_xhi [2048*4096],  g_xlo [2048*4096];
__device__ __nv_bfloat16 g_wphi[12288*4096], g_wplo[12288*4096];
__device__ __nv_bfloat16 g_wohi[4096*4096],  g_wolo[4096*4096];
__device__ __nv_bfloat16 g_qhi [2048*12288], g_qlo [2048*12288];
__device__ float         g_scores[134217728];   // fp32 logits -> in-place split-bf16 P
__device__ __nv_bfloat16 g_ahi [2048*4096],  g_alo [2048*4096];

// ---------------------------------------------------------------------------
// cp.async helpers (used by gemm_nn only)
// ---------------------------------------------------------------------------
__device__ __forceinline__ void cp16(uint32_t s, const void* g) {
    asm volatile("cp.async.cg.shared.global [%0], [%1], 16;" :: "r"(s), "l"(g));
}
__device__ __forceinline__ void cp_commit() { asm volatile("cp.async.commit_group;"); }
__device__ __forceinline__ void cp_wait1()  { asm volatile("cp.async.wait_group 1;"); }
__device__ __forceinline__ void cp_wait0()  { asm volatile("cp.async.wait_group 0;"); }

// ---------------------------------------------------------------------------
// fp32 -> (hi, lo) bf16 split converter (one-shot per array)
// ---------------------------------------------------------------------------
__global__ __launch_bounds__(256) void split_convert(
    const float* __restrict__ in,
    __nv_bfloat16* __restrict__ hi, __nv_bfloat16* __restrict__ lo, int n)
{
    int i = (blockIdx.x * 256 + threadIdx.x) * 4;
    if (i >= n) return;
    float4 v = *reinterpret_cast<const float4*>(in + i);
    float f[4] = {v.x, v.y, v.z, v.w};
    __nv_bfloat16 h[4], l[4];
#pragma unroll
    for (int t = 0; t < 4; t++) {
        h[t] = __float2bfloat16(f[t]);
        l[t] = __float2bfloat16(f[t] - __bfloat162float(h[t]));
    }
    __nv_bfloat162 ph0, ph1, pl0, pl1;
    ph0.x = h[0]; ph0.y = h[1]; ph1.x = h[2]; ph1.y = h[3];
    pl0.x = l[0]; pl0.y = l[1]; pl1.x = l[2]; pl1.y = l[3];
    *reinterpret_cast<__nv_bfloat162*>(hi + i)     = ph0;
    *reinterpret_cast<__nv_bfloat162*>(hi + i + 2) = ph1;
    *reinterpret_cast<__nv_bfloat162*>(lo + i)     = pl0;
    *reinterpret_cast<__nv_bfloat162*>(lo + i + 2) = pl1;
}

// ---------------------------------------------------------------------------
// NT GEMM: 128x64 tile, BK=32, register-staged LDG overlap, static 30KB smem.
// C = alpha * A.B^T via 3-product split (ah*bh + ah*bl + al*bh).
// Output: fp32 (Cf != null, scaled) or split bf16 (Chi/Clo).
// Warps 4(M) x 2(N): each warp 32x32 -> fc[2][2]; 24 mma_sync per BK32
// interval with ONE sync pair (halved barrier rate vs BK16).
// Regs ~110 -> 2 CTAs/SM. smem: sA[2][128*40] + sB[2][64*40] = 30720 B.
// causal: skip block if its 64-col range lies entirely above the diagonal.
// ---------------------------------------------------------------------------
__global__ __launch_bounds__(TPB) void gemm_nt(
    const __nv_bfloat16* __restrict__ Ahi, const __nv_bfloat16* __restrict__ Alo,
    int lda, long long aOff,
    const __nv_bfloat16* __restrict__ Bhi, const __nv_bfloat16* __restrict__ Blo,
    int ldb, long long bOff,
    float* __restrict__ Cf, __nv_bfloat16* __restrict__ Chi, __nv_bfloat16* __restrict__ Clo,
    int ldc, long long cOff,
    int K, float alpha, int causal)
{
    const int bn = blockIdx.x, bm = blockIdx.y, z = blockIdx.z;
    if (causal && bn >= 2 * (bm + 1)) return;      // 64-col block fully above diag

    Ahi += (long long)z * aOff; Alo += (long long)z * aOff;
    Bhi += (long long)z * bOff; Blo += (long long)z * bOff;

    __shared__ __nv_bfloat16 sA[2][128 * 40];      // 20480 B (hi, lo)
    __shared__ __nv_bfloat16 sB[2][64 * 40];       // 10240 B (hi, lo)

    const int tid  = threadIdx.x;
    const int lane = tid & 31;
    const int wid  = tid >> 5;
    const int wr   = wid >> 1;                     // 0..3 (M, 32 rows each)
    const int wc   = wid & 1;                      // 0..1 (N, 32 cols each)

    const int alr = tid >> 1, alc = (tid & 1) * 16;    // A loader: 128r x 2 chunks
    const int blr = tid >> 2, blc = (tid & 3) * 8;     // B loader: 64r x 4 chunks

    uint4 rA[2][2], rB[2];                         // staging: 24 regs

    auto gload = [&](int kt) {
        const size_t ga = (size_t)(bm * 128 + alr) * lda + kt * 32 + alc;
        rA[0][0] = *reinterpret_cast<const uint4*>(Ahi + ga);
        rA[0][1] = *reinterpret_cast<const uint4*>(Ahi + ga + 8);
        rA[1][0] = *reinterpret_cast<const uint4*>(Alo + ga);
        rA[1][1] = *reinterpret_cast<const uint4*>(Alo + ga + 8);
        const size_t gb = (size_t)(bn * 64 + blr) * ldb + kt * 32 + blc;
        rB[0] = *reinterpret_cast<const uint4*>(Bhi + gb);
        rB[1] = *reinterpret_cast<const uint4*>(Blo + gb);
    };
    auto sstore = [&]() {
        const int soa = alr * 40 + alc;
        *reinterpret_cast<uint4*>(&sA[0][soa])     = rA[0][0];
        *reinterpret_cast<uint4*>(&sA[0][soa + 8]) = rA[0][1];
        *reinterpret_cast<uint4*>(&sA[1][soa])     = rA[1][0];
        *reinterpret_cast<uint4*>(&sA[1][soa + 8]) = rA[1][1];
        const int sob = blr * 40 + blc;
        *reinterpret_cast<uint4*>(&sB[0][sob]) = rB[0];
        *reinterpret_cast<uint4*>(&sB[1][sob]) = rB[1];
    };

    wmma::fragment<wmma::accumulator, 16, 16, 16, float> fc[2][2];
#pragma unroll
    for (int i = 0; i < 2; i++)
#pragma unroll
        for (int j = 0; j < 2; j++) wmma::fill_fragment(fc[i][j], 0.0f);

    gload(0); sstore();
    __syncthreads();

    const int ktiles = K >> 5;
    for (int kt = 0; kt < ktiles; kt++) {
        const bool more = (kt + 1 < ktiles);
        if (more) gload(kt + 1);                   // LDGs in flight during MMAs

#pragma unroll
        for (int ks = 0; ks < 2; ks++) {
            wmma::fragment<wmma::matrix_b, 16, 16, 16, __nv_bfloat16, wmma::col_major> fbh[2], fbl[2];
#pragma unroll
            for (int j = 0; j < 2; j++) {
                wmma::load_matrix_sync(fbh[j], &sB[0][(wc * 32 + j * 16) * 40 + ks * 16], 40);
                wmma::load_matrix_sync(fbl[j], &sB[1][(wc * 32 + j * 16) * 40 + ks * 16], 40);
            }
#pragma unroll
            for (int i = 0; i < 2; i++) {
                wmma::fragment<wmma::matrix_a, 16, 16, 16, __nv_bfloat16, wmma::row_major> fah, fal;
                wmma::load_matrix_sync(fah, &sA[0][(wr * 32 + i * 16) * 40 + ks * 16], 40);
                wmma::load_matrix_sync(fal, &sA[1][(wr * 32 + i * 16) * 40 + ks * 16], 40);
#pragma unroll
                for (int j = 0; j < 2; j++) {
                    wmma::mma_sync(fc[i][j], fah, fbh[j], fc[i][j]);
                    wmma::mma_sync(fc[i][j], fah, fbl[j], fc[i][j]);
                    wmma::mma_sync(fc[i][j], fal, fbh[j], fc[i][j]);
                }
            }
        }
        __syncthreads();                           // all warps done reading smem
        if (more) { sstore(); __syncthreads(); }   // refill, then next interval
    }

    if (Cf) {
        float* C = Cf + (long long)z * cOff;
#pragma unroll
        for (int i = 0; i < 2; i++)
#pragma unroll
            for (int j = 0; j < 2; j++) {
#pragma unroll
                for (int e = 0; e < fc[i][j].num_elements; e++) fc[i][j].x[e] *= alpha;
                wmma::store_matrix_sync(
                    C + (size_t)(bm * 128 + wr * 32 + i * 16) * ldc + bn * 64 + wc * 32 + j * 16,
                    fc[i][j], ldc, wmma::mem_row_major);
            }
    } else {
        // split-bf16 epilogue via per-warp 16x16 fp32 staging (reuses sA)
        __syncthreads();
        float* stg = reinterpret_cast<float*>(&sA[0][0]) + wid * 256;
        __nv_bfloat16* CH = Chi + (long long)z * cOff;
        __nv_bfloat16* CL = Clo + (long long)z * cOff;
        const int rr = lane >> 1, cc = (lane & 1) * 8;
#pragma unroll
        for (int i = 0; i < 2; i++) {
#pragma unroll
            for (int j = 0; j < 2; j++) {
                wmma::store_matrix_sync(stg, fc[i][j], 16, wmma::mem_row_major);
                __syncwarp();
                const float* src = stg + rr * 16 + cc;
                __nv_bfloat16 hv[8], lv[8];
#pragma unroll
                for (int t = 0; t < 8; t++) {
                    const float f = src[t];
                    hv[t] = __float2bfloat16(f);
                    lv[t] = __float2bfloat16(f - __bfloat162float(hv[t]));
                }
                const size_t go = ((size_t)bm * 128 + wr * 32 + i * 16 + rr) * (size_t)ldc
                                + (size_t)bn * 64 + wc * 32 + j * 16 + cc;
                *reinterpret_cast<uint4*>(CH + go) = *reinterpret_cast<const uint4*>(hv);
                *reinterpret_cast<uint4*>(CL + go) = *reinterpret_cast<const uint4*>(lv);
                __syncwarp();
            }
        }
    }
}

// ---------------------------------------------------------------------------
// NN GEMM for PV (proven R9 version): BK=16, cp.async double buffer.
// A = in-place split P (row stride 4096 bf16, [2048 hi | 2048 lo] per row).
// ---------------------------------------------------------------------------
__global__ __launch_bounds__(TPB) void gemm_nn(
    const __nv_bfloat16* __restrict__ Ahi, const __nv_bfloat16* __restrict__ Alo,
    int lda, long long aOff,
    const __nv_bfloat16* __restrict__ Bhi, const __nv_bfloat16* __restrict__ Blo,
    int ldb, long long bOff,
    __nv_bfloat16* __restrict__ Chi, __nv_bfloat16* __restrict__ Clo,
    int ldc, long long cOff)
{
    const int bm = blockIdx.y, z = blockIdx.z;
    Ahi += (long long)z * aOff; Alo += (long long)z * aOff;
    Bhi += (long long)z * bOff; Blo += (long long)z * bOff;

    __shared__ char smem_raw[41984];
    __nv_bfloat16* sh = reinterpret_cast<__nv_bfloat16*>(smem_raw);
    const uint32_t sbase = (uint32_t)__cvta_generic_to_shared(sh);

    const int tid  = threadIdx.x;
    const int lane = tid & 31;
    const int wid  = tid >> 5, wr = wid >> 2, wc = wid & 3;

    const int ar = tid >> 1,  ac = (tid & 1) * 8;
    const int br = tid >> 4,  bc = (tid & 15) * 8;

    auto load_tile = [&](int buf, int kt) {
        const int k0 = kt * 16;
        {
            const size_t ga = (size_t)(bm * 128 + ar) * lda + k0 + ac;
            const uint32_t so = (uint32_t)(buf * 12288 + (ar * 24 + ac) * 2);
            cp16(sbase + so,        Ahi + ga);
            cp16(sbase + so + 6144, Alo + ga);
        }
        {
            const size_t gb = (size_t)(k0 + br) * ldb + bc;
            const uint32_t so = (uint32_t)(24576 + buf * 8704 + (br * 136 + bc) * 2);
            cp16(sbase + so,        Bhi + gb);
            cp16(sbase + so + 4352, Blo + gb);
        }
    };

    wmma::fragment<wmma::accumulator, 16, 16, 16, float> fc[4][2];
#pragma unroll
    for (int i = 0; i < 4; i++)
#pragma unroll
        for (int j = 0; j < 2; j++) wmma::fill_fragment(fc[i][j], 0.0f);

    load_tile(0, 0); cp_commit();

    const int ktiles = (bm + 1) * 8;
    for (int kt = 0; kt < ktiles; kt++) {
        const int buf = kt & 1;
        const bool more = (kt + 1 < ktiles);
        if (more) { load_tile(buf ^ 1, kt + 1); cp_commit(); cp_wait1(); }
        else      { cp_wait0(); }
        __syncthreads();

        const __nv_bfloat16* bufA = sh + buf * 6144;
        const __nv_bfloat16* bufB = sh + 12288 + buf * 4352;

        wmma::fragment<wmma::matrix_b, 16, 16, 16, __nv_bfloat16, wmma::row_major> fbh[2], fbl[2];
#pragma unroll
        for (int j = 0; j < 2; j++) {
            wmma::load_matrix_sync(fbh[j], bufB + wc * 32 + j * 16, 136);
            wmma::load_matrix_sync(fbl[j], bufB + 2176 + wc * 32 + j * 16, 136);
        }
#pragma unroll
        for (int i = 0; i < 4; i++) {
            wmma::fragment<wmma::matrix_a, 16, 16, 16, __nv_bfloat16, wmma::row_major> fah, fal;
            wmma::load_matrix_sync(fah, bufA + (wr * 64 + i * 16) * 24, 24);
            wmma::load_matrix_sync(fal, bufA + 3072 + (wr * 64 + i * 16) * 24, 24);
#pragma unroll
            for (int j = 0; j < 2; j++) {
                wmma::mma_sync(fc[i][j], fah, fbh[j], fc[i][j]);
                wmma::mma_sync(fc[i][j], fah, fbl[j], fc[i][j]);
                wmma::mma_sync(fc[i][j], fal, fbh[j], fc[i][j]);
            }
        }
        __syncthreads();
    }

    // split-bf16 epilogue via per-warp 16x16 fp32 staging
    __syncthreads();
    float* stg = reinterpret_cast<float*>(smem_raw) + wid * 256;
    __nv_bfloat16* CH = Chi + (long long)z * cOff;
    __nv_bfloat16* CL = Clo + (long long)z * cOff;
    const int rr = lane >> 1, cc = (lane & 1) * 8;
#pragma unroll
    for (int i = 0; i < 4; i++) {
#pragma unroll
        for (int j = 0; j < 2; j++) {
            wmma::store_matrix_sync(stg, fc[i][j], 16, wmma::mem_row_major);
            __syncwarp();
            const float* src = stg + rr * 16 + cc;
            __nv_bfloat16 hv[8], lv[8];
#pragma unroll
            for (int t = 0; t < 8; t++) {
                const float f = src[t];
                hv[t] = __float2bfloat16(f);
                lv[t] = __float2bfloat16(f - __bfloat162float(hv[t]));
            }
            const size_t go = ((size_t)bm * 128 + wr * 64 + i * 16 + rr) * (size_t)ldc
                            + wc * 32 + j * 16 + cc;
            *reinterpret_cast<uint4*>(CH + go) = *reinterpret_cast<const uint4*>(hv);
            *reinterpret_cast<uint4*>(CL + go) = *reinterpret_cast<const uint4*>(lv);
            __syncwarp();
        }
    }
}

// ---------------------------------------------------------------------------
// Causal row softmax: fp32 logits -> split-bf16 P in-place ([2048 hi | 2048 lo]).
// ---------------------------------------------------------------------------
__global__ __launch_bounds__(256) void softmax_causal()
{
    const int row  = blockIdx.x * 8 + (threadIdx.x >> 5);
    const int lane = threadIdx.x & 31;
    const int hd = row >> 11;
    const int r  = row & 2047;
    float* S = g_scores + (size_t)hd * 4194304 + (size_t)r * 2048;
    __nv_bfloat16* PH = reinterpret_cast<__nv_bfloat16*>(S);
    __nv_bfloat16* PL = PH + 2048;
    const int L = r + 1;

    float vals[64];
    float m = -INFINITY;
#pragma unroll
    for (int i = 0; i < 64; i++) {
        const int c = lane + i * 32;
        float v = (c < L) ? S[c] : -INFINITY;
        vals[i] = v;
        m = fmaxf(m, v);
    }
#pragma unroll
    for (int o = 16; o > 0; o >>= 1) m = fmaxf(m, __shfl_xor_sync(0xffffffffu, m, o));

    float s = 0.0f;
#pragma unroll
    for (int i = 0; i < 64; i++) {
        float e = __expf(vals[i] - m);
        vals[i] = e;
        s += e;
    }
#pragma unroll
    for (int o = 16; o > 0; o >>= 1) s += __shfl_xor_sync(0xffffffffu, s, o);

    const float inv = 1.0f / s;
#pragma unroll
    for (int i = 0; i < 64; i++) {
        const int c = lane + i * 32;
        if (c < L) {
            const float p = vals[i] * inv;
            const __nv_bfloat16 hh = __float2bfloat16(p);
            PH[c] = hh;
            PL[c] = __float2bfloat16(p - __bfloat162float(hh));
        }
    }
    const int Lpad = ((r >> 7) + 1) << 7;
    const __nv_bfloat16 z16 = __float2bfloat16(0.0f);
    for (int c = L + lane; c < Lpad; c += 32) { PH[c] = z16; PL[c] = z16; }
}

// ---------------------------------------------------------------------------
// kernel_launch: static smem only, no attribute calls, no tcgen05.
// ---------------------------------------------------------------------------
extern "C" void kernel_launch(void* const* d_in, const int* in_sizes, int n_in,
                              void* d_out, int out_size)
{
    const float* X  = (const float*)d_in[0];   // hidden_states [1,2048,4096]
    // d_in[1] = attention_mask (pure causal; applied analytically, unused)
    const float* Wp = (const float*)d_in[2];   // w_pack [12288,4096]
    const float* Wo = (const float*)d_in[3];   // w_o    [4096,4096]
    float* out = (float*)d_out;                // [2048,4096] fp32

    __nv_bfloat16 *xhi, *xlo, *wphi, *wplo, *wohi, *wolo, *qhi, *qlo, *ahi, *alo;
    float* scores;
    cudaGetSymbolAddress((void**)&xhi,  g_xhi);  cudaGetSymbolAddress((void**)&xlo,  g_xlo);
    cudaGetSymbolAddress((void**)&wphi, g_wphi); cudaGetSymbolAddress((void**)&wplo, g_wplo);
    cudaGetSymbolAddress((void**)&wohi, g_wohi); cudaGetSymbolAddress((void**)&wolo, g_wolo);
    cudaGetSymbolAddress((void**)&qhi,  g_qhi);  cudaGetSymbolAddress((void**)&qlo,  g_qlo);
    cudaGetSymbolAddress((void**)&ahi,  g_ahi);  cudaGetSymbolAddress((void**)&alo,  g_alo);
    cudaGetSymbolAddress((void**)&scores, g_scores);

    // 0) split conversions (X, Wp, Wo) -> persistent bf16 hi/lo
    split_convert<<<8192,  256>>>(X,  xhi,  xlo,  8388608);
    split_convert<<<49152, 256>>>(Wp, wphi, wplo, 50331648);
    split_convert<<<16384, 256>>>(Wo, wohi, wolo, 16777216);

    // 1) qkv(split) = X @ Wp^T      (12288/64 = 192 n-tiles)
    gemm_nt<<<dim3(192, 16, 1), TPB>>>(
        xhi, xlo, 4096, 0, wphi, wplo, 4096, 0,
        nullptr, qhi, qlo, 12288, 0, 4096, 1.0f, 0);

    // 2) scores_h(fp32) = Q_h @ K_h^T * 1/sqrt(128), causal block skip
    gemm_nt<<<dim3(32, 16, 32), TPB>>>(
        qhi, qlo, 12288, 128, qhi + 4096, qlo + 4096, 12288, 128,
        scores, nullptr, nullptr, 2048, 4194304LL,
        128, 0.08838834764831845f, 1);

    // 3) causal softmax: fp32 logits -> split-bf16 P in-place (+ zero-fill)
    softmax_causal<<<8192, 256>>>();

    // 4) attn(split) = P_h @ V_h (causal K truncation)
    {
        const __nv_bfloat16* phi = reinterpret_cast<const __nv_bfloat16*>(scores);
        const __nv_bfloat16* plo = phi + 2048;
        gemm_nn<<<dim3(1, 16, 32), TPB>>>(
            phi, plo, 4096, 8388608LL,
            qhi + 8192, qlo + 8192, 12288, 128,
            ahi, alo, 4096, 128);
    }

    // 5) out(fp32) = attn @ Wo^T   (4096/64 = 64 n-tiles)
    gemm_nt<<<dim3(64, 16, 1), TPB>>>(
        ahi, alo, 4096, 0, wohi, wolo, 4096, 0,
        out, nullptr, nullptr, 4096, 0, 4096, 1.0f, 0);
}

// round 17
// speedup vs baseline: 1.1094x; 1.1094x over previous
#include <cuda_runtime.h>
#include <cuda_bf16.h>
#include <mma.h>
#include <math.h>
#include <stdint.h>

using namespace nvcuda;

#define TPB 256

// ---------------------------------------------------------------------------
// Persistent scratch (allocation-free __device__ globals, ~943 MB)
// ---------------------------------------------------------------------------
__device__ __nv_bfloat16 g_xhi [2048*4096],  g_xlo [2048*4096];
__device__ __nv_bfloat16 g_wphi[12288*4096], g_wplo[12288*4096];
__device__ __nv_bfloat16 g_wohi[4096*4096],  g_wolo[4096*4096];
__device__ __nv_bfloat16 g_qhi [2048*12288], g_qlo [2048*12288];
__device__ float         g_scores[134217728];   // fp32 logits -> in-place split-bf16 P
__device__ __nv_bfloat16 g_ahi [2048*4096],  g_alo [2048*4096];

// ---------------------------------------------------------------------------
// cp.async helpers
// ---------------------------------------------------------------------------
__device__ __forceinline__ void cp16(uint32_t s, const void* g) {
    asm volatile("cp.async.cg.shared.global [%0], [%1], 16;" :: "r"(s), "l"(g));
}
__device__ __forceinline__ void cp_commit() { asm volatile("cp.async.commit_group;"); }
__device__ __forceinline__ void cp_wait1()  { asm volatile("cp.async.wait_group 1;"); }
__device__ __forceinline__ void cp_wait0()  { asm volatile("cp.async.wait_group 0;"); }

// ---------------------------------------------------------------------------
// fp32 -> (hi, lo) bf16 split converter (one-shot per array)
// ---------------------------------------------------------------------------
__global__ __launch_bounds__(256) void split_convert(
    const float* __restrict__ in,
    __nv_bfloat16* __restrict__ hi, __nv_bfloat16* __restrict__ lo, int n)
{
    int i = (blockIdx.x * 256 + threadIdx.x) * 4;
    if (i >= n) return;
    float4 v = *reinterpret_cast<const float4*>(in + i);
    float f[4] = {v.x, v.y, v.z, v.w};
    __nv_bfloat16 h[4], l[4];
#pragma unroll
    for (int t = 0; t < 4; t++) {
        h[t] = __float2bfloat16(f[t]);
        l[t] = __float2bfloat16(f[t] - __bfloat162float(h[t]));
    }
    __nv_bfloat162 ph0, ph1, pl0, pl1;
    ph0.x = h[0]; ph0.y = h[1]; ph1.x = h[2]; ph1.y = h[3];
    pl0.x = l[0]; pl0.y = l[1]; pl1.x = l[2]; pl1.y = l[3];
    *reinterpret_cast<__nv_bfloat162*>(hi + i)     = ph0;
    *reinterpret_cast<__nv_bfloat162*>(hi + i + 2) = ph1;
    *reinterpret_cast<__nv_bfloat162*>(lo + i)     = pl0;
    *reinterpret_cast<__nv_bfloat162*>(lo + i + 2) = pl1;
}

// ---------------------------------------------------------------------------
// Split-bf16 output epilogue: per-warp 16x16 fp32 staging in reused smem.
// ---------------------------------------------------------------------------
__device__ __forceinline__ void epilogue_split(
    char* smem_raw,
    wmma::fragment<wmma::accumulator, 16, 16, 16, float> (&fc)[4][2],
    __nv_bfloat16* CH, __nv_bfloat16* CL,
    int ldc, size_t row0, size_t col0, int wid, int wr, int wc, int lane)
{
    __syncthreads();
    float* stg = reinterpret_cast<float*>(smem_raw) + wid * 256;
    const int rr = lane >> 1, cc = (lane & 1) * 8;
#pragma unroll
    for (int i = 0; i < 4; i++) {
#pragma unroll
        for (int j = 0; j < 2; j++) {
            wmma::store_matrix_sync(stg, fc[i][j], 16, wmma::mem_row_major);
            __syncwarp();
            const float* src = stg + rr * 16 + cc;
            __nv_bfloat16 hv[8], lv[8];
#pragma unroll
            for (int t = 0; t < 8; t++) {
                const float f = src[t];
                hv[t] = __float2bfloat16(f);
                lv[t] = __float2bfloat16(f - __bfloat162float(hv[t]));
            }
            const size_t go = (row0 + wr * 64 + i * 16 + rr) * (size_t)ldc
                            + col0 + wc * 32 + j * 16 + cc;
            *reinterpret_cast<uint4*>(CH + go) = *reinterpret_cast<const uint4*>(hv);
            *reinterpret_cast<uint4*>(CL + go) = *reinterpret_cast<const uint4*>(lv);
            __syncwarp();
        }
    }
}

// ---------------------------------------------------------------------------
// NT GEMM (R9 geometry): BK=16, cp.async double buffer, 48KB static smem.
// 3-product split; MMA issue order interleaves the two j-chains so that
// same-accumulator HMMAs are spaced 2 issues apart (was back-to-back).
// Per-chain order hh -> hl -> lh preserved => bitwise-identical results.
// ---------------------------------------------------------------------------
__global__ __launch_bounds__(TPB) void gemm_nt(
    const __nv_bfloat16* __restrict__ Ahi, const __nv_bfloat16* __restrict__ Alo,
    int lda, long long aOff,
    const __nv_bfloat16* __restrict__ Bhi, const __nv_bfloat16* __restrict__ Blo,
    int ldb, long long bOff,
    float* __restrict__ Cf, __nv_bfloat16* __restrict__ Chi, __nv_bfloat16* __restrict__ Clo,
    int ldc, long long cOff,
    int K, float alpha, int causal)
{
    const int bn = blockIdx.x, bm = blockIdx.y, z = blockIdx.z;
    if (causal && bn > bm) return;

    Ahi += (long long)z * aOff; Alo += (long long)z * aOff;
    Bhi += (long long)z * bOff; Blo += (long long)z * bOff;

    __shared__ char smem_raw[49152];
    __nv_bfloat16* sh = reinterpret_cast<__nv_bfloat16*>(smem_raw);
    const uint32_t sbase = (uint32_t)__cvta_generic_to_shared(sh);

    const int tid  = threadIdx.x;
    const int lane = tid & 31;
    const int wid  = tid >> 5, wr = wid >> 2, wc = wid & 3;
    const int lr = tid >> 1, lc = (tid & 1) * 8;

    auto load_tile = [&](int buf, int kt) {
        const int k0 = kt * 16;
        const size_t ga = (size_t)(bm * 128 + lr) * lda + k0 + lc;
        const size_t gb = (size_t)(bn * 128 + lr) * ldb + k0 + lc;
        const uint32_t so = (uint32_t)(buf * 12288 + (lr * 24 + lc) * 2);
        cp16(sbase + so,                Ahi + ga);
        cp16(sbase + so + 6144,         Alo + ga);
        cp16(sbase + 24576 + so,        Bhi + gb);
        cp16(sbase + 24576 + so + 6144, Blo + gb);
    };

    wmma::fragment<wmma::accumulator, 16, 16, 16, float> fc[4][2];
#pragma unroll
    for (int i = 0; i < 4; i++)
#pragma unroll
        for (int j = 0; j < 2; j++) wmma::fill_fragment(fc[i][j], 0.0f);

    load_tile(0, 0); cp_commit();

    const int ktiles = K >> 4;
    for (int kt = 0; kt < ktiles; kt++) {
        const int buf = kt & 1;
        const bool more = (kt + 1 < ktiles);
        if (more) { load_tile(buf ^ 1, kt + 1); cp_commit(); cp_wait1(); }
        else      { cp_wait0(); }
        __syncthreads();

        const __nv_bfloat16* bufA = sh + buf * 6144;
        const __nv_bfloat16* bufB = sh + 12288 + buf * 6144;

        wmma::fragment<wmma::matrix_b, 16, 16, 16, __nv_bfloat16, wmma::col_major> fbh[2], fbl[2];
#pragma unroll
        for (int j = 0; j < 2; j++) {
            wmma::load_matrix_sync(fbh[j], bufB + (wc * 32 + j * 16) * 24, 24);
            wmma::load_matrix_sync(fbl[j], bufB + 3072 + (wc * 32 + j * 16) * 24, 24);
        }
#pragma unroll
        for (int i = 0; i < 4; i++) {
            wmma::fragment<wmma::matrix_a, 16, 16, 16, __nv_bfloat16, wmma::row_major> fah, fal;
            wmma::load_matrix_sync(fah, bufA + (wr * 64 + i * 16) * 24, 24);
            wmma::load_matrix_sync(fal, bufA + 3072 + (wr * 64 + i * 16) * 24, 24);
            // term-major: same-accumulator MMAs spaced by the other j-chain
#pragma unroll
            for (int j = 0; j < 2; j++) wmma::mma_sync(fc[i][j], fah, fbh[j], fc[i][j]);
#pragma unroll
            for (int j = 0; j < 2; j++) wmma::mma_sync(fc[i][j], fah, fbl[j], fc[i][j]);
#pragma unroll
            for (int j = 0; j < 2; j++) wmma::mma_sync(fc[i][j], fal, fbh[j], fc[i][j]);
        }
        __syncthreads();
    }

    if (Cf) {
        float* C = Cf + (long long)z * cOff;
#pragma unroll
        for (int i = 0; i < 4; i++)
#pragma unroll
            for (int j = 0; j < 2; j++) {
#pragma unroll
                for (int e = 0; e < fc[i][j].num_elements; e++) fc[i][j].x[e] *= alpha;
                wmma::store_matrix_sync(
                    C + (size_t)(bm * 128 + wr * 64 + i * 16) * ldc + bn * 128 + wc * 32 + j * 16,
                    fc[i][j], ldc, wmma::mem_row_major);
            }
    } else {
        epilogue_split(smem_raw, fc,
                       Chi + (long long)z * cOff, Clo + (long long)z * cOff,
                       ldc, (size_t)bm * 128, (size_t)bn * 128, wid, wr, wc, lane);
    }
}

// ---------------------------------------------------------------------------
// NN GEMM for PV (R9 geometry + same chain-interleave): BK=16, cp.async.
// A = in-place split P (row stride 4096 bf16, [2048 hi | 2048 lo] per row).
// ---------------------------------------------------------------------------
__global__ __launch_bounds__(TPB) void gemm_nn(
    const __nv_bfloat16* __restrict__ Ahi, const __nv_bfloat16* __restrict__ Alo,
    int lda, long long aOff,
    const __nv_bfloat16* __restrict__ Bhi, const __nv_bfloat16* __restrict__ Blo,
    int ldb, long long bOff,
    __nv_bfloat16* __restrict__ Chi, __nv_bfloat16* __restrict__ Clo,
    int ldc, long long cOff)
{
    const int bm = blockIdx.y, z = blockIdx.z;
    Ahi += (long long)z * aOff; Alo += (long long)z * aOff;
    Bhi += (long long)z * bOff; Blo += (long long)z * bOff;

    __shared__ char smem_raw[41984];
    __nv_bfloat16* sh = reinterpret_cast<__nv_bfloat16*>(smem_raw);
    const uint32_t sbase = (uint32_t)__cvta_generic_to_shared(sh);

    const int tid  = threadIdx.x;
    const int lane = tid & 31;
    const int wid  = tid >> 5, wr = wid >> 2, wc = wid & 3;

    const int ar = tid >> 1,  ac = (tid & 1) * 8;
    const int br = tid >> 4,  bc = (tid & 15) * 8;

    auto load_tile = [&](int buf, int kt) {
        const int k0 = kt * 16;
        {
            const size_t ga = (size_t)(bm * 128 + ar) * lda + k0 + ac;
            const uint32_t so = (uint32_t)(buf * 12288 + (ar * 24 + ac) * 2);
            cp16(sbase + so,        Ahi + ga);
            cp16(sbase + so + 6144, Alo + ga);
        }
        {
            const size_t gb = (size_t)(k0 + br) * ldb + bc;
            const uint32_t so = (uint32_t)(24576 + buf * 8704 + (br * 136 + bc) * 2);
            cp16(sbase + so,        Bhi + gb);
            cp16(sbase + so + 4352, Blo + gb);
        }
    };

    wmma::fragment<wmma::accumulator, 16, 16, 16, float> fc[4][2];
#pragma unroll
    for (int i = 0; i < 4; i++)
#pragma unroll
        for (int j = 0; j < 2; j++) wmma::fill_fragment(fc[i][j], 0.0f);

    load_tile(0, 0); cp_commit();

    const int ktiles = (bm + 1) * 8;
    for (int kt = 0; kt < ktiles; kt++) {
        const int buf = kt & 1;
        const bool more = (kt + 1 < ktiles);
        if (more) { load_tile(buf ^ 1, kt + 1); cp_commit(); cp_wait1(); }
        else      { cp_wait0(); }
        __syncthreads();

        const __nv_bfloat16* bufA = sh + buf * 6144;
        const __nv_bfloat16* bufB = sh + 12288 + buf * 4352;

        wmma::fragment<wmma::matrix_b, 16, 16, 16, __nv_bfloat16, wmma::row_major> fbh[2], fbl[2];
#pragma unroll
        for (int j = 0; j < 2; j++) {
            wmma::load_matrix_sync(fbh[j], bufB + wc * 32 + j * 16, 136);
            wmma::load_matrix_sync(fbl[j], bufB + 2176 + wc * 32 + j * 16, 136);
        }
#pragma unroll
        for (int i = 0; i < 4; i++) {
            wmma::fragment<wmma::matrix_a, 16, 16, 16, __nv_bfloat16, wmma::row_major> fah, fal;
            wmma::load_matrix_sync(fah, bufA + (wr * 64 + i * 16) * 24, 24);
            wmma::load_matrix_sync(fal, bufA + 3072 + (wr * 64 + i * 16) * 24, 24);
            // term-major interleave (per-chain order hh -> hl -> lh preserved)
#pragma unroll
            for (int j = 0; j < 2; j++) wmma::mma_sync(fc[i][j], fah, fbh[j], fc[i][j]);
#pragma unroll
            for (int j = 0; j < 2; j++) wmma::mma_sync(fc[i][j], fah, fbl[j], fc[i][j]);
#pragma unroll
            for (int j = 0; j < 2; j++) wmma::mma_sync(fc[i][j], fal, fbh[j], fc[i][j]);
        }
        __syncthreads();
    }

    epilogue_split(smem_raw, fc,
                   Chi + (long long)z * cOff, Clo + (long long)z * cOff,
                   ldc, (size_t)bm * 128, 0, wid, wr, wc, lane);
}

// ---------------------------------------------------------------------------
// Causal row softmax: fp32 logits -> split-bf16 P in-place ([2048 hi | 2048 lo]).
// ---------------------------------------------------------------------------
__global__ __launch_bounds__(256) void softmax_causal()
{
    const int row  = blockIdx.x * 8 + (threadIdx.x >> 5);
    const int lane = threadIdx.x & 31;
    const int hd = row >> 11;
    const int r  = row & 2047;
    float* S = g_scores + (size_t)hd * 4194304 + (size_t)r * 2048;
    __nv_bfloat16* PH = reinterpret_cast<__nv_bfloat16*>(S);
    __nv_bfloat16* PL = PH + 2048;
    const int L = r + 1;

    float vals[64];
    float m = -INFINITY;
#pragma unroll
    for (int i = 0; i < 64; i++) {
        const int c = lane + i * 32;
        float v = (c < L) ? S[c] : -INFINITY;
        vals[i] = v;
        m = fmaxf(m, v);
    }
#pragma unroll
    for (int o = 16; o > 0; o >>= 1) m = fmaxf(m, __shfl_xor_sync(0xffffffffu, m, o));

    float s = 0.0f;
#pragma unroll
    for (int i = 0; i < 64; i++) {
        float e = __expf(vals[i] - m);
        vals[i] = e;
        s += e;
    }
#pragma unroll
    for (int o = 16; o > 0; o >>= 1) s += __shfl_xor_sync(0xffffffffu, s, o);

    const float inv = 1.0f / s;
#pragma unroll
    for (int i = 0; i < 64; i++) {
        const int c = lane + i * 32;
        if (c < L) {
            const float p = vals[i] * inv;
            const __nv_bfloat16 hh = __float2bfloat16(p);
            PH[c] = hh;
            PL[c] = __float2bfloat16(p - __bfloat162float(hh));
        }
    }
    const int Lpad = ((r >> 7) + 1) << 7;
    const __nv_bfloat16 z16 = __float2bfloat16(0.0f);
    for (int c = L + lane; c < Lpad; c += 32) { PH[c] = z16; PL[c] = z16; }
}

// ---------------------------------------------------------------------------
// kernel_launch: static smem only, no attribute calls, no tcgen05.
// ---------------------------------------------------------------------------
extern "C" void kernel_launch(void* const* d_in, const int* in_sizes, int n_in,
                              void* d_out, int out_size)
{
    const float* X  = (const float*)d_in[0];   // hidden_states [1,2048,4096]
    // d_in[1] = attention_mask (pure causal; applied analytically, unused)
    const float* Wp = (const float*)d_in[2];   // w_pack [12288,4096]
    const float* Wo = (const float*)d_in[3];   // w_o    [4096,4096]
    float* out = (float*)d_out;                // [2048,4096] fp32

    __nv_bfloat16 *xhi, *xlo, *wphi, *wplo, *wohi, *wolo, *qhi, *qlo, *ahi, *alo;
    float* scores;
    cudaGetSymbolAddress((void**)&xhi,  g_xhi);  cudaGetSymbolAddress((void**)&xlo,  g_xlo);
    cudaGetSymbolAddress((void**)&wphi, g_wphi); cudaGetSymbolAddress((void**)&wplo, g_wplo);
    cudaGetSymbolAddress((void**)&wohi, g_wohi); cudaGetSymbolAddress((void**)&wolo, g_wolo);
    cudaGetSymbolAddress((void**)&qhi,  g_qhi);  cudaGetSymbolAddress((void**)&qlo,  g_qlo);
    cudaGetSymbolAddress((void**)&ahi,  g_ahi);  cudaGetSymbolAddress((void**)&alo,  g_alo);
    cudaGetSymbolAddress((void**)&scores, g_scores);

    // 0) split conversions (X, Wp, Wo) -> persistent bf16 hi/lo
    split_convert<<<8192,  256>>>(X,  xhi,  xlo,  8388608);
    split_convert<<<49152, 256>>>(Wp, wphi, wplo, 50331648);
    split_convert<<<16384, 256>>>(Wo, wohi, wolo, 16777216);

    // 1) qkv(split) = X @ Wp^T
    gemm_nt<<<dim3(96, 16, 1), TPB>>>(
        xhi, xlo, 4096, 0, wphi, wplo, 4096, 0,
        nullptr, qhi, qlo, 12288, 0, 4096, 1.0f, 0);

    // 2) scores_h(fp32) = Q_h @ K_h^T * 1/sqrt(128), lower-tri blocks only
    gemm_nt<<<dim3(16, 16, 32), TPB>>>(
        qhi, qlo, 12288, 128, qhi + 4096, qlo + 4096, 12288, 128,
        scores, nullptr, nullptr, 2048, 4194304LL,
        128, 0.08838834764831845f, 1);

    // 3) causal softmax: fp32 logits -> split-bf16 P in-place (+ zero-fill)
    softmax_causal<<<8192, 256>>>();

    // 4) attn(split) = P_h @ V_h (causal K truncation)
    {
        const __nv_bfloat16* phi = reinterpret_cast<const __nv_bfloat16*>(scores);
        const __nv_bfloat16* plo = phi + 2048;
        gemm_nn<<<dim3(1, 16, 32), TPB>>>(
            phi, plo, 4096, 8388608LL,
            qhi + 8192, qlo + 8192, 12288, 128,
            ahi, alo, 4096, 128);
    }

    // 5) out(fp32) = attn @ Wo^T
    gemm_nt<<<dim3(32, 16, 1), TPB>>>(
        ahi, alo, 4096, 0, wohi, wolo, 4096, 0,
        out, nullptr, nullptr, 4096, 0, 4096, 1.0f, 0);
}